// round 10
// baseline (speedup 1.0000x reference)
#include <cuda_runtime.h>
#include <cuda_bf16.h>

// Problem shapes
#define NROWS 65536   // B*T = 4096*16
#define HDIMS 512
#define TSEQ 16
#define NHEADS 16
#define HEADD 32

// ---------------------------------------------------------------------------
// Scratch (device globals: allocation-free, graph-safe)
// ---------------------------------------------------------------------------
__device__ __nv_bfloat16 g_xh[(size_t)NROWS * HDIMS];  // LN output hi (bf16 split)
__device__ __nv_bfloat16 g_xl[(size_t)NROWS * HDIMS];  // LN output lo
__device__ __nv_bfloat16 g_wh[4ull * HDIMS * HDIMS];   // weights hi, TRANSPOSED [n][k]
__device__ __nv_bfloat16 g_wl[4ull * HDIMS * HDIMS];   // weights lo, TRANSPOSED [n][k]
__device__ float g_q[(size_t)NROWS * HDIMS];
__device__ float g_k[(size_t)NROWS * HDIMS];
__device__ float g_v[(size_t)NROWS * HDIMS];
__device__ float g_o[(size_t)NROWS * HDIMS];  // attention output (pre-residual)
__device__ float g_f[(size_t)NROWS * HDIMS];  // FF1 output

// ---------------------------------------------------------------------------
// bf16 hi/lo split: x ~= hi + lo, hi = rn(x), lo = rn(x - hi)
// ---------------------------------------------------------------------------
__device__ __forceinline__ void bsplit(float y, __nv_bfloat16& h, __nv_bfloat16& l) {
    h = __float2bfloat16(y);
    l = __float2bfloat16(y - __bfloat162float(h));
}

// mma.sync m16n8k16 row.col bf16 -> f32 accumulate (legacy tensor path, sm_80+)
__device__ __forceinline__ void mma_bf16(float* c, unsigned a0, unsigned a1,
                                         unsigned a2, unsigned a3,
                                         unsigned b0, unsigned b1) {
    asm volatile(
        "mma.sync.aligned.m16n8k16.row.col.f32.bf16.bf16.f32 "
        "{%0,%1,%2,%3}, {%4,%5,%6,%7}, {%8,%9}, {%0,%1,%2,%3};"
        : "+f"(c[0]), "+f"(c[1]), "+f"(c[2]), "+f"(c[3])
        : "r"(a0), "r"(a1), "r"(a2), "r"(a3), "r"(b0), "r"(b1));
}

// ---------------------------------------------------------------------------
// Weight convert: split W[k][n] fp32 into bf16 hi/lo, TRANSPOSED to [n][k]
// grid (1024, 4) x 256 thr; mat = blockIdx.y selects {Wq, Wk, Wv, ff1w}
// ---------------------------------------------------------------------------
__global__ void convw_kernel(const float* __restrict__ w0, const float* __restrict__ w1,
                             const float* __restrict__ w2, const float* __restrict__ w3) {
    int mat = blockIdx.y;
    const float* W = (mat == 0) ? w0 : (mat == 1) ? w1 : (mat == 2) ? w2 : w3;
    int e = blockIdx.x * blockDim.x + threadIdx.x;  // 0..262143, e = k*512 + n
    int k = e >> 9, n = e & 511;
    __nv_bfloat16 h, l;
    bsplit(W[e], h, l);
    size_t off = (size_t)mat * HDIMS * HDIMS + (size_t)n * HDIMS + k;
    g_wh[off] = h;
    g_wl[off] = l;
}

// ---------------------------------------------------------------------------
// Kernel 1: x = structural + pe[t] + pos_cc + pos_blr ; LayerNorm -> g_xh/g_xl
// one block (128 threads) per row of 512; each thread owns one float4
// ---------------------------------------------------------------------------
__global__ void addln_kernel(const float* __restrict__ s, const float* __restrict__ cc,
                             const float* __restrict__ blr, const float* __restrict__ pe,
                             const float* __restrict__ gamma, const float* __restrict__ beta) {
    int n = blockIdx.x;
    int t = n & (TSEQ - 1);
    int tid = threadIdx.x;
    size_t rb = (size_t)n * HDIMS;

    float4 a = *(const float4*)(s + rb + tid * 4);
    float4 b = *(const float4*)(cc + rb + tid * 4);
    float4 c = *(const float4*)(blr + rb + tid * 4);
    float4 p = *(const float4*)(pe + (size_t)t * HDIMS + tid * 4);
    float4 x;
    x.x = a.x + b.x + c.x + p.x;
    x.y = a.y + b.y + c.y + p.y;
    x.z = a.z + b.z + c.z + p.z;
    x.w = a.w + b.w + c.w + p.w;

    float ls = x.x + x.y + x.z + x.w;
    float lq = x.x * x.x + x.y * x.y + x.z * x.z + x.w * x.w;
    __shared__ float r0[4], r1[4];
#pragma unroll
    for (int o = 16; o; o >>= 1) {
        ls += __shfl_down_sync(0xffffffffu, ls, o);
        lq += __shfl_down_sync(0xffffffffu, lq, o);
    }
    if ((tid & 31) == 0) { r0[tid >> 5] = ls; r1[tid >> 5] = lq; }
    __syncthreads();
    float sum = r0[0] + r0[1] + r0[2] + r0[3];
    float sq  = r1[0] + r1[1] + r1[2] + r1[3];
    float mu = sum * (1.0f / HDIMS);
    float var = sq * (1.0f / HDIMS) - mu * mu;
    float rstd = rsqrtf(var + 1e-5f);

    float4 g = *(const float4*)(gamma + tid * 4);
    float4 be = *(const float4*)(beta + tid * 4);
    float y0 = (x.x - mu) * rstd * g.x + be.x;
    float y1 = (x.y - mu) * rstd * g.y + be.y;
    float y2 = (x.z - mu) * rstd * g.z + be.z;
    float y3 = (x.w - mu) * rstd * g.w + be.w;

    __nv_bfloat16 h0, h1, h2, h3, l0, l1, l2, l3;
    bsplit(y0, h0, l0); bsplit(y1, h1, l1); bsplit(y2, h2, l2); bsplit(y3, h3, l3);
    __nv_bfloat162 vh0; vh0.x = h0; vh0.y = h1;
    __nv_bfloat162 vh1; vh1.x = h2; vh1.y = h3;
    __nv_bfloat162 vl0; vl0.x = l0; vl0.y = l1;
    __nv_bfloat162 vl1; vl1.x = l2; vl1.y = l3;
    *(__nv_bfloat162*)(g_xh + rb + tid * 4)     = vh0;
    *(__nv_bfloat162*)(g_xh + rb + tid * 4 + 2) = vh1;
    *(__nv_bfloat162*)(g_xl + rb + tid * 4)     = vl0;
    *(__nv_bfloat162*)(g_xl + rb + tid * 4 + 2) = vl1;
}

// ---------------------------------------------------------------------------
// residual + LayerNorm: x = g_o + structural ; LN -> g_xh/g_xl
// ---------------------------------------------------------------------------
__global__ void resln_kernel(const float* __restrict__ s,
                             const float* __restrict__ gamma, const float* __restrict__ beta) {
    int n = blockIdx.x;
    int tid = threadIdx.x;
    size_t rb = (size_t)n * HDIMS;

    float4 a = *(const float4*)(g_o + rb + tid * 4);
    float4 b = *(const float4*)(s + rb + tid * 4);
    float4 x;
    x.x = a.x + b.x; x.y = a.y + b.y; x.z = a.z + b.z; x.w = a.w + b.w;

    float ls = x.x + x.y + x.z + x.w;
    float lq = x.x * x.x + x.y * x.y + x.z * x.z + x.w * x.w;
    __shared__ float r0[4], r1[4];
#pragma unroll
    for (int o = 16; o; o >>= 1) {
        ls += __shfl_down_sync(0xffffffffu, ls, o);
        lq += __shfl_down_sync(0xffffffffu, lq, o);
    }
    if ((tid & 31) == 0) { r0[tid >> 5] = ls; r1[tid >> 5] = lq; }
    __syncthreads();
    float sum = r0[0] + r0[1] + r0[2] + r0[3];
    float sq  = r1[0] + r1[1] + r1[2] + r1[3];
    float mu = sum * (1.0f / HDIMS);
    float var = sq * (1.0f / HDIMS) - mu * mu;
    float rstd = rsqrtf(var + 1e-5f);

    float4 g = *(const float4*)(gamma + tid * 4);
    float4 be = *(const float4*)(beta + tid * 4);
    float y0 = (x.x - mu) * rstd * g.x + be.x;
    float y1 = (x.y - mu) * rstd * g.y + be.y;
    float y2 = (x.z - mu) * rstd * g.z + be.z;
    float y3 = (x.w - mu) * rstd * g.w + be.w;

    __nv_bfloat16 h0, h1, h2, h3, l0, l1, l2, l3;
    bsplit(y0, h0, l0); bsplit(y1, h1, l1); bsplit(y2, h2, l2); bsplit(y3, h3, l3);
    __nv_bfloat162 vh0; vh0.x = h0; vh0.y = h1;
    __nv_bfloat162 vh1; vh1.x = h2; vh1.y = h3;
    __nv_bfloat162 vl0; vl0.x = l0; vl0.y = l1;
    __nv_bfloat162 vl1; vl1.x = l2; vl1.y = l3;
    *(__nv_bfloat162*)(g_xh + rb + tid * 4)     = vh0;
    *(__nv_bfloat162*)(g_xh + rb + tid * 4 + 2) = vh1;
    *(__nv_bfloat162*)(g_xl + rb + tid * 4)     = vl0;
    *(__nv_bfloat162*)(g_xl + rb + tid * 4 + 2) = vl1;
}

// ---------------------------------------------------------------------------
// MMA GEMM core: C[65536,512] = (ah+al) @ (bh+bl)^T  via 3-pass bf16 split
//   C = ah*bh + ah*bl + al*bh   (fp32 accumulate; al*bl dropped ~2^-18)
// A: [row][k] bf16 row-major. B: [n][k] bf16 (pre-transposed) = col-major operand.
// 128x128 block, 8 warps (2x4), warp tile 64x32, k-chunk 16, double-buffered.
// ---------------------------------------------------------------------------
__device__ __forceinline__ void mma_gemm_core(const __nv_bfloat16* __restrict__ ah,
                                              const __nv_bfloat16* __restrict__ al,
                                              const __nv_bfloat16* __restrict__ bh,
                                              const __nv_bfloat16* __restrict__ bl,
                                              float* __restrict__ C,
                                              const float* __restrict__ bias,
                                              const float* __restrict__ prelu,
                                              int col0, int row0) {
    // row stride 12 uints: frag loads (g*12+tig) mod 32 cover 32 distinct banks
    __shared__ unsigned AsH[2][128][12], AsL[2][128][12];
    __shared__ unsigned BsH[2][128][12], BsL[2][128][12];

    int tid = threadIdx.x;
    int row = tid >> 1, half = tid & 1;       // tile-load mapping
    int wid = tid >> 5, lane = tid & 31;
    int wr = wid >> 2, wc = wid & 3;          // warp grid 2x4
    int g = lane >> 2, tig = lane & 3;        // mma fragment lane decomposition

    float acc[4][4][4];
#pragma unroll
    for (int i = 0; i < 4; i++)
#pragma unroll
        for (int j = 0; j < 4; j++)
#pragma unroll
            for (int q = 0; q < 4; q++) acc[i][j][q] = 0.0f;

    // per-thread gmem slices: one uint4 (8 bf16) per array per chunk
    const uint4* pAh = (const uint4*)(ah + (size_t)(row0 + row) * HDIMS + half * 8);
    const uint4* pAl = (const uint4*)(al + (size_t)(row0 + row) * HDIMS + half * 8);
    const uint4* pBh = (const uint4*)(bh + (size_t)(col0 + row) * HDIMS + half * 8);
    const uint4* pBl = (const uint4*)(bl + (size_t)(col0 + row) * HDIMS + half * 8);

    uint4 vAh = pAh[0], vAl = pAl[0], vBh = pBh[0], vBl = pBl[0];
    *(uint4*)&AsH[0][row][half * 4] = vAh;
    *(uint4*)&AsL[0][row][half * 4] = vAl;
    *(uint4*)&BsH[0][row][half * 4] = vBh;
    *(uint4*)&BsL[0][row][half * 4] = vBl;
    __syncthreads();

    int buf = 0;
    for (int c = 0; c < 32; c++) {
        bool has_next = (c < 31);
        if (has_next) {
            vAh = pAh[(c + 1) * 2]; vAl = pAl[(c + 1) * 2];
            vBh = pBh[(c + 1) * 2]; vBl = pBl[(c + 1) * 2];
        }

        // B fragments for all 4 n-frags (kept live across mf loop)
        unsigned bhf[4][2], blf[4][2];
#pragma unroll
        for (int nf = 0; nf < 4; nf++) {
            int n = wc * 32 + nf * 8 + g;
            bhf[nf][0] = BsH[buf][n][tig];
            bhf[nf][1] = BsH[buf][n][tig + 4];
            blf[nf][0] = BsL[buf][n][tig];
            blf[nf][1] = BsL[buf][n][tig + 4];
        }

#pragma unroll
        for (int mf = 0; mf < 4; mf++) {
            int r = wr * 64 + mf * 16 + g;
            unsigned a0h = AsH[buf][r][tig],     a1h = AsH[buf][r + 8][tig];
            unsigned a2h = AsH[buf][r][tig + 4], a3h = AsH[buf][r + 8][tig + 4];
            unsigned a0l = AsL[buf][r][tig],     a1l = AsL[buf][r + 8][tig];
            unsigned a2l = AsL[buf][r][tig + 4], a3l = AsL[buf][r + 8][tig + 4];
#pragma unroll
            for (int nf = 0; nf < 4; nf++) {
                mma_bf16(acc[mf][nf], a0h, a1h, a2h, a3h, bhf[nf][0], bhf[nf][1]);
                mma_bf16(acc[mf][nf], a0h, a1h, a2h, a3h, blf[nf][0], blf[nf][1]);
                mma_bf16(acc[mf][nf], a0l, a1l, a2l, a3l, bhf[nf][0], bhf[nf][1]);
            }
        }

        if (has_next) {
            int nb = buf ^ 1;
            *(uint4*)&AsH[nb][row][half * 4] = vAh;
            *(uint4*)&AsL[nb][row][half * 4] = vAl;
            *(uint4*)&BsH[nb][row][half * 4] = vBh;
            *(uint4*)&BsL[nb][row][half * 4] = vBl;
        }
        __syncthreads();
        buf ^= 1;
    }

    // epilogue: c0,c1 at (r, col..col+1); c2,c3 at (r+8, col..col+1)
    bool hb = (bias != nullptr);
    float pa = hb ? prelu[0] : 0.0f;
#pragma unroll
    for (int mf = 0; mf < 4; mf++) {
        int r = row0 + wr * 64 + mf * 16 + g;
#pragma unroll
        for (int nf = 0; nf < 4; nf++) {
            int col = col0 + wc * 32 + nf * 8 + tig * 2;
            float o0 = acc[mf][nf][0], o1 = acc[mf][nf][1];
            float o2 = acc[mf][nf][2], o3 = acc[mf][nf][3];
            if (hb) {
                float b0 = bias[col], b1 = bias[col + 1];
                o0 += b0; o1 += b1; o2 += b0; o3 += b1;
                o0 = o0 > 0.0f ? o0 : o0 * pa;
                o1 = o1 > 0.0f ? o1 : o1 * pa;
                o2 = o2 > 0.0f ? o2 : o2 * pa;
                o3 = o3 > 0.0f ? o3 : o3 * pa;
            }
            float2 lo; lo.x = o0; lo.y = o1;
            float2 hi; hi.x = o2; hi.y = o3;
            *(float2*)(C + (size_t)r * HDIMS + col) = lo;
            *(float2*)(C + (size_t)(r + 8) * HDIMS + col) = hi;
        }
    }
}

// Fused QKV. Grid (12, 512): z = x%3 (fastest) -> same A row-tile blocks adjacent
__global__ void __launch_bounds__(256, 2) qkv_mma_kernel() {
    int z = blockIdx.x % 3;
    int colblk = blockIdx.x / 3;
    size_t woff = (size_t)z * HDIMS * HDIMS;
    float* C = (z == 0) ? g_q : (z == 1) ? g_k : g_v;
    mma_gemm_core(g_xh, g_xl, g_wh + woff, g_wl + woff, C, nullptr, nullptr,
                  colblk * 128, blockIdx.y * 128);
}

__global__ void __launch_bounds__(256, 2)
ff1_mma_kernel(const float* __restrict__ b, const float* __restrict__ pa) {
    size_t woff = 3ull * HDIMS * HDIMS;
    mma_gemm_core(g_xh, g_xl, g_wh + woff, g_wl + woff, g_f, b, pa,
                  blockIdx.x * 128, blockIdx.y * 128);
}

// ---------------------------------------------------------------------------
// Attention: one block (128 thr) per (b, head). T=16, HD=32, causal softmax.
// ---------------------------------------------------------------------------
__global__ void attn_kernel() {
    __shared__ float qs[16][36], ks[16][36], vs[16][36];
    __shared__ float ps[16][17];

    int bh = blockIdx.x;
    int b = bh >> 4, h = bh & 15;
    int tid = threadIdx.x;
    size_t base = (size_t)b * TSEQ * HDIMS + h * HEADD;

    int row = tid >> 3, c4 = (tid & 7) << 2;
    size_t off = base + (size_t)row * HDIMS + c4;
    *(float4*)&qs[row][c4] = *(const float4*)(g_q + off);
    *(float4*)&ks[row][c4] = *(const float4*)(g_k + off);
    *(float4*)&vs[row][c4] = *(const float4*)(g_v + off);
    __syncthreads();

#pragma unroll
    for (int p = tid; p < 256; p += 128) {
        int i = p >> 4, j = p & 15;
        float sc = -1e9f;
        if (j <= i) {
            float s = 0.0f;
#pragma unroll
            for (int d = 0; d < HEADD; d++) s += qs[i][d] * ks[j][d];
            sc = s * 0.17677669529663687f;  // 1/sqrt(32)
        }
        ps[i][j] = sc;
    }
    __syncthreads();

    if (tid < 16) {
        int i = tid;
        float m = -1e30f;
        for (int j = 0; j <= i; j++) m = fmaxf(m, ps[i][j]);
        float sum = 0.0f;
        for (int j = 0; j < 16; j++) {
            float e = (j <= i) ? __expf(ps[i][j] - m) : 0.0f;
            ps[i][j] = e;
            sum += e;
        }
        float inv = 1.0f / sum;
        for (int j = 0; j < 16; j++) ps[i][j] *= inv;
    }
    __syncthreads();

    float4 acc = make_float4(0.0f, 0.0f, 0.0f, 0.0f);
#pragma unroll
    for (int j = 0; j < 16; j++) {
        float w = ps[row][j];
        float4 vv = *(const float4*)&vs[j][c4];
        acc.x += w * vv.x;
        acc.y += w * vv.y;
        acc.z += w * vv.z;
        acc.w += w * vv.w;
    }
    *(float4*)(g_o + off) = acc;
}

// ---------------------------------------------------------------------------
// FF2: out[n, 0:2] = g_f[n,:] @ ff2_w[512,2] + ff2_b ; one warp per row
// ---------------------------------------------------------------------------
__global__ void ff2_kernel(const float* __restrict__ w, const float* __restrict__ b,
                           float* __restrict__ out) {
    int gw = (blockIdx.x * blockDim.x + threadIdx.x) >> 5;
    int lane = threadIdx.x & 31;
    const float* x = g_f + (size_t)gw * HDIMS;
    const float2* w2 = (const float2*)w;
    float a0 = 0.0f, a1 = 0.0f;
#pragma unroll
    for (int k0 = lane * 4; k0 < HDIMS; k0 += 128) {
        float4 xv = *(const float4*)(x + k0);
        float2 w0 = w2[k0 + 0];
        float2 w1 = w2[k0 + 1];
        float2 w2v = w2[k0 + 2];
        float2 w3 = w2[k0 + 3];
        a0 = fmaf(xv.x, w0.x, a0); a1 = fmaf(xv.x, w0.y, a1);
        a0 = fmaf(xv.y, w1.x, a0); a1 = fmaf(xv.y, w1.y, a1);
        a0 = fmaf(xv.z, w2v.x, a0); a1 = fmaf(xv.z, w2v.y, a1);
        a0 = fmaf(xv.w, w3.x, a0); a1 = fmaf(xv.w, w3.y, a1);
    }
#pragma unroll
    for (int o = 16; o; o >>= 1) {
        a0 += __shfl_down_sync(0xffffffffu, a0, o);
        a1 += __shfl_down_sync(0xffffffffu, a1, o);
    }
    if (lane == 0) {
        out[2 * gw] = a0 + b[0];
        out[2 * gw + 1] = a1 + b[1];
    }
}

// ---------------------------------------------------------------------------
// Launch
// ---------------------------------------------------------------------------
extern "C" void kernel_launch(void* const* d_in, const int* in_sizes, int n_in,
                              void* d_out, int out_size) {
    const float* structural = (const float*)d_in[0];
    const float* cc    = (const float*)d_in[1];
    const float* blr   = (const float*)d_in[2];
    // d_in[3] = exist_nodes (unused by the reference math)
    const float* Wq    = (const float*)d_in[4];
    const float* Wk    = (const float*)d_in[5];
    const float* Wv    = (const float*)d_in[6];
    const float* pe    = (const float*)d_in[7];
    const float* gamma = (const float*)d_in[8];
    const float* beta  = (const float*)d_in[9];
    const float* ff1w  = (const float*)d_in[10];
    const float* ff1b  = (const float*)d_in[11];
    const float* prelu = (const float*)d_in[12];
    const float* ff2w  = (const float*)d_in[13];
    const float* ff2b  = (const float*)d_in[14];
    float* out = (float*)d_out;

    convw_kernel<<<dim3(1024, 4), 256>>>(Wq, Wk, Wv, ff1w);

    addln_kernel<<<NROWS, 128>>>(structural, cc, blr, pe, gamma, beta);

    qkv_mma_kernel<<<dim3(12, 512), 256>>>();

    attn_kernel<<<NROWS, 128>>>();  // B*NH = 65536 blocks

    resln_kernel<<<NROWS, 128>>>(structural, gamma, beta);

    ff1_mma_kernel<<<dim3(4, 512), 256>>>(ff1b, prelu);

    ff2_kernel<<<NROWS / 8, 256>>>(ff2w, ff2b, out);
}

// round 17
// speedup vs baseline: 1.0962x; 1.0962x over previous
#include <cuda_runtime.h>
#include <cuda_bf16.h>
#include <cstdint>

// Problem shapes
#define NROWS 65536   // B*T = 4096*16
#define HDIMS 512
#define TSEQ 16
#define NHEADS 16
#define HEADD 32

// ---------------------------------------------------------------------------
// Scratch (device globals: allocation-free, graph-safe)
// ---------------------------------------------------------------------------
__device__ __nv_bfloat16 g_xh[(size_t)NROWS * HDIMS];  // LN output hi (bf16 split)
__device__ __nv_bfloat16 g_xl[(size_t)NROWS * HDIMS];  // LN output lo
__device__ __nv_bfloat16 g_wh[4ull * HDIMS * HDIMS];   // weights hi, TRANSPOSED [n][k]
__device__ __nv_bfloat16 g_wl[4ull * HDIMS * HDIMS];   // weights lo, TRANSPOSED [n][k]
__device__ float g_q[(size_t)NROWS * HDIMS];
__device__ float g_k[(size_t)NROWS * HDIMS];
__device__ float g_v[(size_t)NROWS * HDIMS];
__device__ float g_o[(size_t)NROWS * HDIMS];
__device__ float g_f[(size_t)NROWS * HDIMS];

// ---------------------------------------------------------------------------
// bf16 hi/lo split
// ---------------------------------------------------------------------------
__device__ __forceinline__ void bsplit(float y, __nv_bfloat16& h, __nv_bfloat16& l) {
    h = __float2bfloat16(y);
    l = __float2bfloat16(y - __bfloat162float(h));
}

__device__ __forceinline__ uint32_t smem_u32(const void* p) {
    uint32_t a;
    asm("{ .reg .u64 t; cvta.to.shared.u64 t, %1; cvt.u32.u64 %0, t; }" : "=r"(a) : "l"(p));
    return a;
}

// mma.sync m16n8k16 row.col bf16 -> f32 accumulate (validated in R10 pass)
__device__ __forceinline__ void mma_bf16(float* c, unsigned a0, unsigned a1,
                                         unsigned a2, unsigned a3,
                                         unsigned b0, unsigned b1) {
    asm volatile(
        "mma.sync.aligned.m16n8k16.row.col.f32.bf16.bf16.f32 "
        "{%0,%1,%2,%3}, {%4,%5,%6,%7}, {%8,%9}, {%0,%1,%2,%3};"
        : "+f"(c[0]), "+f"(c[1]), "+f"(c[2]), "+f"(c[3])
        : "r"(a0), "r"(a1), "r"(a2), "r"(a3), "r"(b0), "r"(b1));
}

// ldmatrix x4: 4 8x8 b16 tiles; lane i supplies row addr of tile i/8.
__device__ __forceinline__ void ldsm4(unsigned* r, uint32_t addr) {
    asm volatile("ldmatrix.sync.aligned.m8n8.x4.shared.b16 {%0,%1,%2,%3}, [%4];"
                 : "=r"(r[0]), "=r"(r[1]), "=r"(r[2]), "=r"(r[3]) : "r"(addr));
}

// ---------------------------------------------------------------------------
// Weight convert: split W[k][n] fp32 into bf16 hi/lo, TRANSPOSED to [n][k]
// ---------------------------------------------------------------------------
__global__ void convw_kernel(const float* __restrict__ w0, const float* __restrict__ w1,
                             const float* __restrict__ w2, const float* __restrict__ w3) {
    int mat = blockIdx.y;
    const float* W = (mat == 0) ? w0 : (mat == 1) ? w1 : (mat == 2) ? w2 : w3;
    int e = blockIdx.x * blockDim.x + threadIdx.x;  // e = k*512 + n
    int k = e >> 9, n = e & 511;
    __nv_bfloat16 h, l;
    bsplit(W[e], h, l);
    size_t off = (size_t)mat * HDIMS * HDIMS + (size_t)n * HDIMS + k;
    g_wh[off] = h;
    g_wl[off] = l;
}

// ---------------------------------------------------------------------------
// addln: x = structural + pe[t] + pos_cc + pos_blr ; LayerNorm -> bf16 hi/lo
// ---------------------------------------------------------------------------
__global__ void addln_kernel(const float* __restrict__ s, const float* __restrict__ cc,
                             const float* __restrict__ blr, const float* __restrict__ pe,
                             const float* __restrict__ gamma, const float* __restrict__ beta) {
    int n = blockIdx.x;
    int t = n & (TSEQ - 1);
    int tid = threadIdx.x;
    size_t rb = (size_t)n * HDIMS;

    float4 a = *(const float4*)(s + rb + tid * 4);
    float4 b = *(const float4*)(cc + rb + tid * 4);
    float4 c = *(const float4*)(blr + rb + tid * 4);
    float4 p = *(const float4*)(pe + (size_t)t * HDIMS + tid * 4);
    float4 x;
    x.x = a.x + b.x + c.x + p.x;
    x.y = a.y + b.y + c.y + p.y;
    x.z = a.z + b.z + c.z + p.z;
    x.w = a.w + b.w + c.w + p.w;

    float ls = x.x + x.y + x.z + x.w;
    float lq = x.x * x.x + x.y * x.y + x.z * x.z + x.w * x.w;
    __shared__ float r0[4], r1[4];
#pragma unroll
    for (int o = 16; o; o >>= 1) {
        ls += __shfl_down_sync(0xffffffffu, ls, o);
        lq += __shfl_down_sync(0xffffffffu, lq, o);
    }
    if ((tid & 31) == 0) { r0[tid >> 5] = ls; r1[tid >> 5] = lq; }
    __syncthreads();
    float sum = r0[0] + r0[1] + r0[2] + r0[3];
    float sq  = r1[0] + r1[1] + r1[2] + r1[3];
    float mu = sum * (1.0f / HDIMS);
    float var = sq * (1.0f / HDIMS) - mu * mu;
    float rstd = rsqrtf(var + 1e-5f);

    float4 g = *(const float4*)(gamma + tid * 4);
    float4 be = *(const float4*)(beta + tid * 4);
    float y0 = (x.x - mu) * rstd * g.x + be.x;
    float y1 = (x.y - mu) * rstd * g.y + be.y;
    float y2 = (x.z - mu) * rstd * g.z + be.z;
    float y3 = (x.w - mu) * rstd * g.w + be.w;

    __nv_bfloat16 h0, h1, h2, h3, l0, l1, l2, l3;
    bsplit(y0, h0, l0); bsplit(y1, h1, l1); bsplit(y2, h2, l2); bsplit(y3, h3, l3);
    __nv_bfloat162 vh0; vh0.x = h0; vh0.y = h1;
    __nv_bfloat162 vh1; vh1.x = h2; vh1.y = h3;
    __nv_bfloat162 vl0; vl0.x = l0; vl0.y = l1;
    __nv_bfloat162 vl1; vl1.x = l2; vl1.y = l3;
    *(__nv_bfloat162*)(g_xh + rb + tid * 4)     = vh0;
    *(__nv_bfloat162*)(g_xh + rb + tid * 4 + 2) = vh1;
    *(__nv_bfloat162*)(g_xl + rb + tid * 4)     = vl0;
    *(__nv_bfloat162*)(g_xl + rb + tid * 4 + 2) = vl1;
}

__global__ void resln_kernel(const float* __restrict__ s,
                             const float* __restrict__ gamma, const float* __restrict__ beta) {
    int n = blockIdx.x;
    int tid = threadIdx.x;
    size_t rb = (size_t)n * HDIMS;

    float4 a = *(const float4*)(g_o + rb + tid * 4);
    float4 b = *(const float4*)(s + rb + tid * 4);
    float4 x;
    x.x = a.x + b.x; x.y = a.y + b.y; x.z = a.z + b.z; x.w = a.w + b.w;

    float ls = x.x + x.y + x.z + x.w;
    float lq = x.x * x.x + x.y * x.y + x.z * x.z + x.w * x.w;
    __shared__ float r0[4], r1[4];
#pragma unroll
    for (int o = 16; o; o >>= 1) {
        ls += __shfl_down_sync(0xffffffffu, ls, o);
        lq += __shfl_down_sync(0xffffffffu, lq, o);
    }
    if ((tid & 31) == 0) { r0[tid >> 5] = ls; r1[tid >> 5] = lq; }
    __syncthreads();
    float sum = r0[0] + r0[1] + r0[2] + r0[3];
    float sq  = r1[0] + r1[1] + r1[2] + r1[3];
    float mu = sum * (1.0f / HDIMS);
    float var = sq * (1.0f / HDIMS) - mu * mu;
    float rstd = rsqrtf(var + 1e-5f);

    float4 g = *(const float4*)(gamma + tid * 4);
    float4 be = *(const float4*)(beta + tid * 4);
    float y0 = (x.x - mu) * rstd * g.x + be.x;
    float y1 = (x.y - mu) * rstd * g.y + be.y;
    float y2 = (x.z - mu) * rstd * g.z + be.z;
    float y3 = (x.w - mu) * rstd * g.w + be.w;

    __nv_bfloat16 h0, h1, h2, h3, l0, l1, l2, l3;
    bsplit(y0, h0, l0); bsplit(y1, h1, l1); bsplit(y2, h2, l2); bsplit(y3, h3, l3);
    __nv_bfloat162 vh0; vh0.x = h0; vh0.y = h1;
    __nv_bfloat162 vh1; vh1.x = h2; vh1.y = h3;
    __nv_bfloat162 vl0; vl0.x = l0; vl0.y = l1;
    __nv_bfloat162 vl1; vl1.x = l2; vl1.y = l3;
    *(__nv_bfloat162*)(g_xh + rb + tid * 4)     = vh0;
    *(__nv_bfloat162*)(g_xh + rb + tid * 4 + 2) = vh1;
    *(__nv_bfloat162*)(g_xl + rb + tid * 4)     = vl0;
    *(__nv_bfloat162*)(g_xl + rb + tid * 4 + 2) = vl1;
}

// ---------------------------------------------------------------------------
// MMA GEMM core (R10-validated math, ldmatrix fragment loads):
// C = ah*bh + ah*bl + al*bh, fp32 accum. 128x128 block, 8 warps (2x4),
// warp tile 64x32, k-chunk 16, double-buffered. LDSM replaces 48 LDS/chunk.
// ---------------------------------------------------------------------------
__device__ __forceinline__ void mma_gemm_core(const __nv_bfloat16* __restrict__ ah,
                                              const __nv_bfloat16* __restrict__ al,
                                              const __nv_bfloat16* __restrict__ bh,
                                              const __nv_bfloat16* __restrict__ bl,
                                              float* __restrict__ C,
                                              const float* __restrict__ bias,
                                              const float* __restrict__ prelu,
                                              int col0, int row0) {
    // row stride 12 uints (48B): LDSM tile rows hit 16B-banks 3i mod 8 = permutation
    __shared__ unsigned AsH[2][128][12], AsL[2][128][12];
    __shared__ unsigned BsH[2][128][12], BsL[2][128][12];

    int tid = threadIdx.x;
    int row = tid >> 1, half = tid & 1;       // tile-load mapping
    int wid = tid >> 5, lane = tid & 31;
    int wr = wid >> 2, wc = wid & 3;          // warp grid 2x4
    int g = lane >> 2, tig = lane & 3;        // mma fragment lane decomposition
    int lrow = lane & 7, seg = lane >> 3;     // ldmatrix lane decomposition

    float acc[4][4][4];
#pragma unroll
    for (int i = 0; i < 4; i++)
#pragma unroll
        for (int j = 0; j < 4; j++)
#pragma unroll
            for (int q = 0; q < 4; q++) acc[i][j][q] = 0.0f;

    // ldmatrix byte offsets within one [128][12]-uint buffer.
    // A x4 tile order {row-half, k-half}: seg&1 -> +8 rows, seg>>1 -> +16B (k8-15)
    // B x4 tile order {k-half, row-half}: seg&1 -> +16B,    seg>>1 -> +8 rows
    uint32_t a_off[4], b_off[2];
#pragma unroll
    for (int mf = 0; mf < 4; mf++)
        a_off[mf] = ((uint32_t)(wr * 64 + mf * 16 + (seg & 1) * 8 + lrow) * 12u +
                     (uint32_t)(seg >> 1) * 4u) * 4u;
#pragma unroll
    for (int p = 0; p < 2; p++)
        b_off[p] = ((uint32_t)(wc * 32 + p * 16 + (seg >> 1) * 8 + lrow) * 12u +
                    (uint32_t)(seg & 1) * 4u) * 4u;

    uint32_t baseAH[2] = { smem_u32(&AsH[0][0][0]), smem_u32(&AsH[1][0][0]) };
    uint32_t baseAL[2] = { smem_u32(&AsL[0][0][0]), smem_u32(&AsL[1][0][0]) };
    uint32_t baseBH[2] = { smem_u32(&BsH[0][0][0]), smem_u32(&BsH[1][0][0]) };
    uint32_t baseBL[2] = { smem_u32(&BsL[0][0][0]), smem_u32(&BsL[1][0][0]) };

    // per-thread gmem slices: one uint4 (8 bf16) per array per chunk
    const uint4* pAh = (const uint4*)(ah + (size_t)(row0 + row) * HDIMS + half * 8);
    const uint4* pAl = (const uint4*)(al + (size_t)(row0 + row) * HDIMS + half * 8);
    const uint4* pBh = (const uint4*)(bh + (size_t)(col0 + row) * HDIMS + half * 8);
    const uint4* pBl = (const uint4*)(bl + (size_t)(col0 + row) * HDIMS + half * 8);

    uint4 vAh = pAh[0], vAl = pAl[0], vBh = pBh[0], vBl = pBl[0];
    *(uint4*)&AsH[0][row][half * 4] = vAh;
    *(uint4*)&AsL[0][row][half * 4] = vAl;
    *(uint4*)&BsH[0][row][half * 4] = vBh;
    *(uint4*)&BsL[0][row][half * 4] = vBl;
    __syncthreads();

    int buf = 0;
    for (int c = 0; c < 32; c++) {
        bool has_next = (c < 31);
        if (has_next) {
            vAh = pAh[(c + 1) * 2]; vAl = pAl[(c + 1) * 2];
            vBh = pBh[(c + 1) * 2]; vBl = pBl[(c + 1) * 2];
        }

        // B fragments: 2 LDSM.x4 per hi/lo cover all 4 n-frags
        unsigned bhf[4][2], blf[4][2];
#pragma unroll
        for (int p = 0; p < 2; p++) {
            unsigned t[4];
            ldsm4(t, baseBH[buf] + b_off[p]);
            bhf[2 * p][0] = t[0]; bhf[2 * p][1] = t[1];
            bhf[2 * p + 1][0] = t[2]; bhf[2 * p + 1][1] = t[3];
            ldsm4(t, baseBL[buf] + b_off[p]);
            blf[2 * p][0] = t[0]; blf[2 * p][1] = t[1];
            blf[2 * p + 1][0] = t[2]; blf[2 * p + 1][1] = t[3];
        }

#pragma unroll
        for (int mf = 0; mf < 4; mf++) {
            unsigned ah4[4], al4[4];
            ldsm4(ah4, baseAH[buf] + a_off[mf]);
            ldsm4(al4, baseAL[buf] + a_off[mf]);
#pragma unroll
            for (int nf = 0; nf < 4; nf++) {
                mma_bf16(acc[mf][nf], ah4[0], ah4[1], ah4[2], ah4[3], bhf[nf][0], bhf[nf][1]);
                mma_bf16(acc[mf][nf], ah4[0], ah4[1], ah4[2], ah4[3], blf[nf][0], blf[nf][1]);
                mma_bf16(acc[mf][nf], al4[0], al4[1], al4[2], al4[3], bhf[nf][0], bhf[nf][1]);
            }
        }

        if (has_next) {
            int nb = buf ^ 1;
            *(uint4*)&AsH[nb][row][half * 4] = vAh;
            *(uint4*)&AsL[nb][row][half * 4] = vAl;
            *(uint4*)&BsH[nb][row][half * 4] = vBh;
            *(uint4*)&BsL[nb][row][half * 4] = vBl;
        }
        __syncthreads();
        buf ^= 1;
    }

    // epilogue: c0,c1 at (r, col..col+1); c2,c3 at (r+8, col..col+1)  [R10-validated]
    bool hb = (bias != nullptr);
    float pa = hb ? prelu[0] : 0.0f;
#pragma unroll
    for (int mf = 0; mf < 4; mf++) {
        int r = row0 + wr * 64 + mf * 16 + g;
#pragma unroll
        for (int nf = 0; nf < 4; nf++) {
            int col = col0 + wc * 32 + nf * 8 + tig * 2;
            float o0 = acc[mf][nf][0], o1 = acc[mf][nf][1];
            float o2 = acc[mf][nf][2], o3 = acc[mf][nf][3];
            if (hb) {
                float b0 = bias[col], b1 = bias[col + 1];
                o0 += b0; o1 += b1; o2 += b0; o3 += b1;
                o0 = o0 > 0.0f ? o0 : o0 * pa;
                o1 = o1 > 0.0f ? o1 : o1 * pa;
                o2 = o2 > 0.0f ? o2 : o2 * pa;
                o3 = o3 > 0.0f ? o3 : o3 * pa;
            }
            float2 lo; lo.x = o0; lo.y = o1;
            float2 hi; hi.x = o2; hi.y = o3;
            *(float2*)(C + (size_t)r * HDIMS + col) = lo;
            *(float2*)(C + (size_t)(r + 8) * HDIMS + col) = hi;
        }
    }
}

// Fused QKV. Grid (12, 512): z = x%3 (fastest) -> same A row-tile blocks adjacent
__global__ void __launch_bounds__(256, 2) qkv_mma_kernel() {
    int z = blockIdx.x % 3;
    int colblk = blockIdx.x / 3;
    size_t woff = (size_t)z * HDIMS * HDIMS;
    float* C = (z == 0) ? g_q : (z == 1) ? g_k : g_v;
    mma_gemm_core(g_xh, g_xl, g_wh + woff, g_wl + woff, C, nullptr, nullptr,
                  colblk * 128, blockIdx.y * 128);
}

__global__ void __launch_bounds__(256, 2)
ff1_mma_kernel(const float* __restrict__ b, const float* __restrict__ pa) {
    size_t woff = 3ull * HDIMS * HDIMS;
    mma_gemm_core(g_xh, g_xl, g_wh + woff, g_wl + woff, g_f, b, pa,
                  blockIdx.x * 128, blockIdx.y * 128);
}

// ---------------------------------------------------------------------------
// Attention: one block (128 thr) per (b, head). float4 dot products (L1 fix).
// ---------------------------------------------------------------------------
__global__ void attn_kernel() {
    __shared__ float qs[16][36], ks[16][36], vs[16][36];
    __shared__ float ps[16][17];

    int bh = blockIdx.x;
    int b = bh >> 4, h = bh & 15;
    int tid = threadIdx.x;
    size_t base = (size_t)b * TSEQ * HDIMS + h * HEADD;

    int row = tid >> 3, c4 = (tid & 7) << 2;
    size_t off = base + (size_t)row * HDIMS + c4;
    *(float4*)&qs[row][c4] = *(const float4*)(g_q + off);
    *(float4*)&ks[row][c4] = *(const float4*)(g_k + off);
    *(float4*)&vs[row][c4] = *(const float4*)(g_v + off);
    __syncthreads();

#pragma unroll
    for (int p = tid; p < 256; p += 128) {
        int i = p >> 4, j = p & 15;
        float sc = -1e9f;
        if (j <= i) {
            const float4* qv = (const float4*)&qs[i][0];
            const float4* kv = (const float4*)&ks[j][0];
            float s = 0.0f;
#pragma unroll
            for (int d = 0; d < 8; d++) {
                float4 qa = qv[d], kb = kv[d];
                s += qa.x * kb.x + qa.y * kb.y + qa.z * kb.z + qa.w * kb.w;
            }
            sc = s * 0.17677669529663687f;  // 1/sqrt(32)
        }
        ps[i][j] = sc;
    }
    __syncthreads();

    if (tid < 16) {
        int i = tid;
        float m = -1e30f;
        for (int j = 0; j <= i; j++) m = fmaxf(m, ps[i][j]);
        float sum = 0.0f;
        for (int j = 0; j < 16; j++) {
            float e = (j <= i) ? __expf(ps[i][j] - m) : 0.0f;
            ps[i][j] = e;
            sum += e;
        }
        float inv = 1.0f / sum;
        for (int j = 0; j < 16; j++) ps[i][j] *= inv;
    }
    __syncthreads();

    float4 acc = make_float4(0.0f, 0.0f, 0.0f, 0.0f);
#pragma unroll
    for (int j = 0; j < 16; j++) {
        float w = ps[row][j];
        float4 vv = *(const float4*)&vs[j][c4];
        acc.x += w * vv.x;
        acc.y += w * vv.y;
        acc.z += w * vv.z;
        acc.w += w * vv.w;
    }
    *(float4*)(g_o + off) = acc;
}

// ---------------------------------------------------------------------------
// FF2: out[n, 0:2] = g_f[n,:] @ ff2_w[512,2] + ff2_b ; one warp per row
// ---------------------------------------------------------------------------
__global__ void ff2_kernel(const float* __restrict__ w, const float* __restrict__ b,
                           float* __restrict__ out) {
    int gw = (blockIdx.x * blockDim.x + threadIdx.x) >> 5;
    int lane = threadIdx.x & 31;
    const float* x = g_f + (size_t)gw * HDIMS;
    const float2* w2 = (const float2*)w;
    float a0 = 0.0f, a1 = 0.0f;
#pragma unroll
    for (int k0 = lane * 4; k0 < HDIMS; k0 += 128) {
        float4 xv = *(const float4*)(x + k0);
        float2 w0 = w2[k0 + 0];
        float2 w1 = w2[k0 + 1];
        float2 w2v = w2[k0 + 2];
        float2 w3 = w2[k0 + 3];
        a0 = fmaf(xv.x, w0.x, a0); a1 = fmaf(xv.x, w0.y, a1);
        a0 = fmaf(xv.y, w1.x, a0); a1 = fmaf(xv.y, w1.y, a1);
        a0 = fmaf(xv.z, w2v.x, a0); a1 = fmaf(xv.z, w2v.y, a1);
        a0 = fmaf(xv.w, w3.x, a0); a1 = fmaf(xv.w, w3.y, a1);
    }
#pragma unroll
    for (int o = 16; o; o >>= 1) {
        a0 += __shfl_down_sync(0xffffffffu, a0, o);
        a1 += __shfl_down_sync(0xffffffffu, a1, o);
    }
    if (lane == 0) {
        out[2 * gw] = a0 + b[0];
        out[2 * gw + 1] = a1 + b[1];
    }
}

// ---------------------------------------------------------------------------
// Launch
// ---------------------------------------------------------------------------
extern "C" void kernel_launch(void* const* d_in, const int* in_sizes, int n_in,
                              void* d_out, int out_size) {
    const float* structural = (const float*)d_in[0];
    const float* cc    = (const float*)d_in[1];
    const float* blr   = (const float*)d_in[2];
    // d_in[3] = exist_nodes (unused by the reference math)
    const float* Wq    = (const float*)d_in[4];
    const float* Wk    = (const float*)d_in[5];
    const float* Wv    = (const float*)d_in[6];
    const float* pe    = (const float*)d_in[7];
    const float* gamma = (const float*)d_in[8];
    const float* beta  = (const float*)d_in[9];
    const float* ff1w  = (const float*)d_in[10];
    const float* ff1b  = (const float*)d_in[11];
    const float* prelu = (const float*)d_in[12];
    const float* ff2w  = (const float*)d_in[13];
    const float* ff2b  = (const float*)d_in[14];
    float* out = (float*)d_out;

    convw_kernel<<<dim3(1024, 4), 256>>>(Wq, Wk, Wv, ff1w);

    addln_kernel<<<NROWS, 128>>>(structural, cc, blr, pe, gamma, beta);

    qkv_mma_kernel<<<dim3(12, 512), 256>>>();

    attn_kernel<<<NROWS, 128>>>();  // B*NH = 65536 blocks

    resln_kernel<<<NROWS, 128>>>(structural, gamma, beta);

    ff1_mma_kernel<<<dim3(4, 512), 256>>>(ff1b, prelu);

    ff2_kernel<<<NROWS / 8, 256>>>(ff2w, ff2b, out);
}